// round 4
// baseline (speedup 1.0000x reference)
#include <cuda_runtime.h>

typedef unsigned long long u64;

#define BD   32
#define LD   513
#define DD   8
#define HD   64
#define WINW 16
#define NW   32
#define OUTD 4
#define NPAIR 28
#define NTH  512

// W1 quad-packed in GLOBAL: gW1Q[b4*128 + r] = W1[r][4b4..4b4+3]
__device__ ulonglong2 gW1Q[16 * 128];

__device__ const signed char PI_[NPAIR] = {0,0,0,0,0,0,0, 1,1,1,1,1,1, 2,2,2,2,2, 3,3,3,3, 4,4,4, 5,5, 6};
__device__ const signed char PJ_[NPAIR] = {1,2,3,4,5,6,7, 2,3,4,5,6,7, 3,4,5,6,7, 4,5,6,7, 5,6,7, 6,7, 7};

// ---------- fast math ----------
__device__ __forceinline__ float ex2f(float x){ float y; asm("ex2.approx.f32 %0, %1;" : "=f"(y) : "f"(x)); return y; }
__device__ __forceinline__ float rcpf(float x){ float y; asm("rcp.approx.f32 %0, %1;" : "=f"(y) : "f"(x)); return y; }
__device__ __forceinline__ float sigf(float x){ return rcpf(1.0f + ex2f(-1.4426950408889634f * x)); }
__device__ __forceinline__ float tanh_fast(float x){
    float t = ex2f(2.8853900817779268f * x);
    return 1.0f - 2.0f * rcpf(t + 1.0f);
}
__device__ __forceinline__ float lipswish(float x, float* dout){
    float s = sigf(x);
    *dout = 0.909f * s * fmaf(x, 1.0f - s, 1.0f);
    return 0.909f * x * s;
}

// ---------- packed f32x2 ----------
__device__ __forceinline__ u64 f2u(float x, float y){ u64 v; asm("mov.b64 %0, {%1, %2};" : "=l"(v) : "f"(x), "f"(y)); return v; }
__device__ __forceinline__ float hsum2(u64 v){ float a, b; asm("mov.b64 {%0, %1}, %2;" : "=f"(a), "=f"(b) : "l"(v)); return a + b; }
__device__ __forceinline__ u64 fma2(u64 a, u64 b, u64 c){ u64 d; asm("fma.rn.f32x2 %0, %1, %2, %3;" : "=l"(d) : "l"(a), "l"(b), "l"(c)); return d; }

__device__ __forceinline__ int pidx(int i, int j) { return (i * (13 - i)) / 2 + j - 1; }

// ---- smem layout (float offsets) ----
// 0      : W2Q  (16384)  ulonglong2[32*128]: W2Q[r4*128+k] = W2[k][4r4..+3]
// 16384  : W3Q  (32768)  ulonglong2[16*512]: W3Q[q*512+row] = W3[row][4q..+3]
// 49152  : sG   (1152)
// 50304  : sy(64) symid(64) sk1(64) scm(64)
// 50560  : sh1(128) ss1(128) sh2(128) ss2(128)
// 51072  : sf(512)
// 51584  : stp(512)
// 52096  : sVpT(512)   [aliased by sp]
// 52608  : sD1F(1024)
// 53632  : sPart(4096) [sEF aliases sPart chunk 0; sInc at init]
// total 57728 floats = 230,912 B
#define OFF_W2Q   0
#define OFF_W3Q   16384
#define OFF_G     49152
#define OFF_Y     50304
#define OFF_YMID  50368
#define OFF_K1    50432
#define OFF_CM    50496
#define OFF_H1    50560
#define OFF_S1    50688
#define OFF_H2    50816
#define OFF_S2    50944
#define OFF_F     51072
#define OFF_TP    51584
#define OFF_VPT   52096
#define OFF_SP    52096
#define OFF_D1F   52608
#define OFF_PART  53632
#define SMEM_FLOATS 57728

extern __shared__ float sm[];

// PH = 1: first Heun stage (writes sk1, symid). PH = 2: second stage (updates sy).
template<int PH>
__device__ __forceinline__ void vf_apply(
    int tid, const float* __restrict__ yv,
    const float* __restrict__ b1, const float* __restrict__ b2, const float* __restrict__ b3,
    const float* __restrict__ gvec, float dt)
{
    const ulonglong2* W2Q = (const ulonglong2*)(sm + OFF_W2Q);
    const ulonglong2* W3Q = (const ulonglong2*)(sm + OFF_W3Q);
    float* sh1 = sm + OFF_H1;  float* ss1 = sm + OFF_S1;
    float* sh2 = sm + OFF_H2;  float* ss2 = sm + OFF_S2;
    float* sf  = sm + OFF_F;   float* stp = sm + OFF_TP;
    float* sVpT= sm + OFF_VPT; float* sD1F= sm + OFF_D1F;
    float* sp  = sm + OFF_SP;  float* sPart = sm + OFF_PART;
    float* sEF = sm + OFF_PART;   // alias: chunk 0 of sPart
    const float* scm = sm + OFF_CM;

    // ---- L1 forward (128 threads), W1 from global ----
    if (tid < 128) {
        const int r = tid;
        u64 a0 = 0ull, a1 = 0ull;
        #pragma unroll
        for (int b4 = 0; b4 < 16; b4++) {
            ulonglong2 w = gW1Q[b4 * 128 + r];
            ulonglong2 yq = *(const ulonglong2*)(yv + 4 * b4);
            a0 = fma2(w.x, yq.x, a0);
            a1 = fma2(w.y, yq.y, a1);
        }
        float pre = b1[r] + hsum2(a0) + hsum2(a1);
        float d; sh1[r] = lipswish(pre, &d); ss1[r] = d;
    }
    __syncthreads();

    // ---- L2 forward (128 threads) ----
    if (tid < 128) {
        const int k = tid;
        u64 a0 = 0ull, a1 = 0ull;
        #pragma unroll 8
        for (int r4 = 0; r4 < 32; r4++) {
            ulonglong2 w = W2Q[r4 * 128 + k];
            ulonglong2 h = *(const ulonglong2*)(sh1 + 4 * r4);
            a0 = fma2(w.x, h.x, a0);
            a1 = fma2(w.y, h.y, a1);
        }
        float pre = b2[k] + hsum2(a0) + hsum2(a1);
        float d; sh2[k] = lipswish(pre, &d); ss2[k] = d;
    }
    __syncthreads();

    // ---- L3 forward (512 threads), W3 from smem ----
    {
        const int row = tid;
        u64 a0 = 0ull, a1 = 0ull;
        #pragma unroll 4
        for (int q = 0; q < 16; q++) {
            ulonglong2 w = W3Q[q * 512 + row];
            ulonglong2 h = *(const ulonglong2*)(sh2 + 4 * q);
            a0 = fma2(w.x, h.x, a0);
            a1 = fma2(w.y, h.y, a1);
        }
        float f = tanh_fast(b3[row] + hsum2(a0) + hsum2(a1));
        sf[row] = f;
        stp[row] = 1.0f - f * f;
    }
    __syncthreads();

    // ---- Vp: sVpT[j][b] = sum_i f[i*64+b] * cmat[i][j] ----
    {
        const int j = tid >> 6, bq = tid & 63;
        float acc = 0.0f;
        #pragma unroll
        for (int i = 0; i < 8; i++) acc += sf[i * 64 + bq] * scm[i * 8 + j];
        sVpT[j * 64 + bq] = acc;
    }
    __syncthreads();

    // ---- U1' partial (512 threads; c = chunk over b, r), W1 from global ----
    {
        const int c = tid >> 7, r = tid & 127;
        u64 acc[8] = {0ull,0ull,0ull,0ull,0ull,0ull,0ull,0ull};
        #pragma unroll
        for (int ib = 0; ib < 4; ib++) {
            const int b4 = 4 * c + ib;
            ulonglong2 w = gW1Q[b4 * 128 + r];
            #pragma unroll
            for (int j = 0; j < 8; j++) {
                ulonglong2 d = *(const ulonglong2*)(sVpT + j * 64 + 4 * b4);
                acc[j] = fma2(w.x, d.x, acc[j]);
                acc[j] = fma2(w.y, d.y, acc[j]);
            }
        }
        #pragma unroll
        for (int j = 0; j < 8; j++) sPart[c * 1024 + j * 128 + r] = hsum2(acc[j]);
    }
    __syncthreads();

    // ---- U1' reduce -> D1F[j][r] ----
    {
        const int j = tid >> 7, r = tid & 127;
        const float s = ss1[r];
        #pragma unroll
        for (int jj = j; jj < 8; jj += 4) {
            float v = sPart[jj * 128 + r] + sPart[1024 + jj * 128 + r]
                    + sPart[2048 + jj * 128 + r] + sPart[3072 + jj * 128 + r];
            sD1F[jj * 128 + r] = s * v;
        }
    }
    __syncthreads();

    // ---- U2' partial (512 threads; c = chunk over r, k) ----
    {
        const int c = tid >> 7, k = tid & 127;
        u64 acc[8] = {0ull,0ull,0ull,0ull,0ull,0ull,0ull,0ull};
        #pragma unroll
        for (int ir = 0; ir < 8; ir++) {
            const int r4 = 8 * c + ir;
            ulonglong2 w = W2Q[r4 * 128 + k];
            #pragma unroll
            for (int j = 0; j < 8; j++) {
                ulonglong2 d = *(const ulonglong2*)(sD1F + j * 128 + 4 * r4);
                acc[j] = fma2(w.x, d.x, acc[j]);
                acc[j] = fma2(w.y, d.y, acc[j]);
            }
        }
        #pragma unroll
        for (int j = 0; j < 8; j++) sPart[c * 1024 + j * 128 + k] = hsum2(acc[j]);
    }
    __syncthreads();

    // ---- U2' reduce -> EF[j][k]  (sEF aliases sPart chunk 0: read-then-write own slot) ----
    {
        const int j = tid >> 7, k = tid & 127;
        const float s = ss2[k];
        #pragma unroll
        for (int jj = j; jj < 8; jj += 4) {
            float v = sPart[jj * 128 + k] + sPart[1024 + jj * 128 + k]
                    + sPart[2048 + jj * 128 + k] + sPart[3072 + jj * 128 + k];
            sEF[jj * 128 + k] = s * v;
        }
    }
    __syncthreads();

    // ---- diag pass: row = tid, j = row >> 6, W3 from smem ----
    {
        const int row = tid, j = row >> 6;
        const float* Ej = sEF + j * 128;
        u64 a0 = 0ull, a1 = 0ull;
        #pragma unroll 4
        for (int q = 0; q < 16; q++) {
            ulonglong2 w = W3Q[q * 512 + row];
            ulonglong2 e = *(const ulonglong2*)(Ej + 4 * q);
            a0 = fma2(w.x, e.x, a0);
            a1 = fma2(w.y, e.y, a1);
        }
        sp[row] = stp[row] * (hsum2(a0) + hsum2(a1));   // sp aliases sVpT (dead)
    }
    __syncthreads();

    // ---- combine + Heun update ----
    if (tid < 64) {
        float acc = 0.0f;
        #pragma unroll
        for (int j = 0; j < 8; j++) acc += sp[j * 64 + tid];
        #pragma unroll
        for (int i = 0; i < 8; i++) acc += gvec[i] * sf[i * 64 + tid];
        if (PH == 1) {
            sm[OFF_K1 + tid] = acc;
            sm[OFF_YMID + tid] = sm[OFF_Y + tid] + dt * acc;
        } else {
            sm[OFF_Y + tid] = sm[OFF_Y + tid] + 0.5f * dt * (sm[OFF_K1 + tid] + acc);
        }
    }
    __syncthreads();
}

__global__ void __launch_bounds__(NTH, 1) ncde_kernel(
    const float* __restrict__ cv,
    const float* __restrict__ Wi1, const float* __restrict__ bi1,
    const float* __restrict__ Wi2, const float* __restrict__ bi2,
    const float* __restrict__ W1, const float* __restrict__ b1,
    const float* __restrict__ W2, const float* __restrict__ b2,
    const float* __restrict__ W3, const float* __restrict__ b3,
    const float* __restrict__ Wr, const float* __restrict__ br,
    const float* __restrict__ shiftp,
    float* __restrict__ out)
{
    const int tid = threadIdx.x;
    const int b = blockIdx.x;

    const float dt = (float)WINW / (float)(LD - 1);
    const float inv_dt = 1.0f / dt;

    ulonglong2* W2Q = (ulonglong2*)(sm + OFF_W2Q);
    ulonglong2* W3Q = (ulonglong2*)(sm + OFF_W3Q);
    float* sG   = sm + OFF_G;
    float* sy   = sm + OFF_Y;
    float* sh1  = sm + OFF_H1;
    float* sPart= sm + OFF_PART;

    // ---- init: pack weights ----
    for (int idx = tid; idx < 16 * 128; idx += NTH) {
        int b4 = idx >> 7, r = idx & 127;
        float4 v = ((const float4*)W1)[r * 16 + b4];
        ulonglong2 q; q.x = f2u(v.x, v.y); q.y = f2u(v.z, v.w);
        gW1Q[idx] = q;   // all CTAs write identical values
    }
    for (int idx = tid; idx < 32 * 128; idx += NTH) {
        int r4 = idx >> 7, k = idx & 127;
        float4 v = ((const float4*)W2)[k * 32 + r4];
        ulonglong2 q; q.x = f2u(v.x, v.y); q.y = f2u(v.z, v.w);
        W2Q[idx] = q;
    }
    for (int idx = tid; idx < 16 * 512; idx += NTH) {
        int q16 = idx >> 9, row = idx & 511;
        float4 v = ((const float4*)W3)[row * 32 + q16];
        ulonglong2 q; q.x = f2u(v.x, v.y); q.y = f2u(v.z, v.w);
        W3Q[idx] = q;
    }
    // path increments into sPart
    const float* cvb = cv + (size_t)b * LD * DD;
    for (int idx = tid; idx < 512 * 8; idx += NTH) {
        sPart[idx] = cvb[idx + 8] - cvb[idx];
    }
    __syncthreads();

    // ---- window log-signatures (pre-divided by dt) ----
    const float* sInc = sPart;
    for (int idx = tid; idx < NW * NPAIR; idx += NTH) {
        int w = idx / NPAIR, p = idx % NPAIR;
        int i = PI_[p], j = PJ_[p];
        float acc = 0.f, pi = 0.f, pj = 0.f;
        const float* base = sInc + w * 16 * 8;
        #pragma unroll
        for (int s = 0; s < 16; s++) {
            float ii = base[s * 8 + i], jj = base[s * 8 + j];
            acc += pi * jj - pj * ii;
            pi += ii; pj += jj;
        }
        sG[w * 36 + 8 + p] = 0.5f * acc * inv_dt;
    }
    for (int idx = tid; idx < NW * 8; idx += NTH) {
        int w = idx >> 3, d2 = idx & 7;
        sG[w * 36 + d2] = (cvb[(16 * w + 16) * 8 + d2] - cvb[16 * w * 8 + d2]) * inv_dt;
    }
    // y0 layer1 into sh1
    if (tid < 64) {
        float acc = bi1[tid];
        #pragma unroll
        for (int d2 = 0; d2 < 8; d2++) acc += Wi1[tid * 8 + d2] * cvb[d2];
        float dd;
        sh1[tid] = lipswish(acc, &dd);
    }
    __syncthreads();
    // y0 layer2
    if (tid < 64) {
        float acc = bi2[tid];
        #pragma unroll 8
        for (int h = 0; h < 64; h++) acc += Wi2[tid * 64 + h] * sh1[h];
        sy[tid] = acc;
    }
    __syncthreads();

    const float shiftv = *shiftp;

    // ---- main Heun loop ----
    for (int n = 0; n < NW; n++) {
        const float* gvec = sG + n * 36;
        if (tid < 64) {
            int i = tid >> 3, j = tid & 7;
            float v = 0.0f;
            if (i < j) v = gvec[8 + pidx(i, j)];
            else if (i > j) v = -gvec[8 + pidx(j, i)];
            sm[OFF_CM + tid] = v;
        } else if (tid < 68) {
            int rt = tid - 64;
            float acc = br[rt] + shiftv;
            #pragma unroll 8
            for (int a = 0; a < 64; a++) acc += Wr[rt * 64 + a] * sy[a];
            out[b * (NW + 1) * OUTD + n * OUTD + rt] = acc;
        }
        __syncthreads();

        vf_apply<1>(tid, sm + OFF_Y,    b1, b2, b3, gvec, dt);
        vf_apply<2>(tid, sm + OFF_YMID, b1, b2, b3, gvec, dt);
    }

    // final readout (index NW)
    if (tid < 4) {
        float acc = br[tid] + shiftv;
        #pragma unroll 8
        for (int a = 0; a < 64; a++) acc += Wr[tid * 64 + a] * sy[a];
        out[b * (NW + 1) * OUTD + NW * OUTD + tid] = acc;
    }
}

extern "C" void kernel_launch(void* const* d_in, const int* in_sizes, int n_in,
                              void* d_out, int out_size) {
    (void)in_sizes; (void)n_in; (void)out_size;
    const size_t smem = SMEM_FLOATS * sizeof(float);  // 230,912 B
    cudaFuncSetAttribute(ncde_kernel, cudaFuncAttributeMaxDynamicSharedMemorySize, (int)smem);
    ncde_kernel<<<BD, NTH, smem>>>(
        (const float*)d_in[0],
        (const float*)d_in[1], (const float*)d_in[2],
        (const float*)d_in[3], (const float*)d_in[4],
        (const float*)d_in[5], (const float*)d_in[6],
        (const float*)d_in[7], (const float*)d_in[8],
        (const float*)d_in[9], (const float*)d_in[10],
        (const float*)d_in[11], (const float*)d_in[12],
        (const float*)d_in[13],
        (float*)d_out);
}